// round 5
// baseline (speedup 1.0000x reference)
#include <cuda_runtime.h>
#include <math.h>

// Fixed shapes for BlurredMem_61950608278069
#define BS 128
#define W  256
#define N  2048
#define R  4
#define EPSF 1e-8f
#define CH 4                  // k2 n-chunks (512 n per block)
#define NC 32                 // k4 n-chunks (64 cols per block)
#define CCOL 64
#define SMN_STRIDE 68         // padded row stride (floats): conflict-free & 16B aligned

// Output layout: m_read (BS,R,W) | M_new (BS,W,N) | read_wt (BS,R,N)
#define OFF_MNEW (BS*R*W)
#define OFF_RWT  (BS*R*W + BS*W*N)

// -------- scratch (device globals) --------
__device__ float  g_wk[BS*W];          // UNNORMALIZED write key (relu'd)
__device__ float2 g_wmer[BS*W];        // (write_m, erase_vec)
__device__ float4 g_kn4[BS*W];         // normalized read keys (r packed)
__device__ float  g_we[BS*N];          // exp(-cos) unnormalized write weights
__device__ float  g_Zw_part[BS*CH];    // per-block partial sums of g_we
__device__ float  g_Zr_part[BS*NC*R];  // per-chunk partial Zr
__device__ float  g_mr_part[BS*NC*W*R];// per-chunk partial m_read (16MB)

// dynamic smem layout for k4_fused (bytes):
//  s_kn    [0,     4096)   float4[256]
//  s_mn    [4096,  73728)  float[256][68]
//  s_e     [73728, 74752)  float[4][64]
//  s_wmer  [74752, 76800)  float2[256]
//  s_part  [76800, 81920)  float[256*5]
//  s_red   [81920, 81952)  float[8]
#define K4_SMEM 81952

// -------- block reduction: warp shuffles + one smem pass (256 threads) ----
template<int NV>
__device__ __forceinline__ void blk_reduce_sum(float (&v)[NV], float* sbuf) {
    const int lane = threadIdx.x & 31, wid = threadIdx.x >> 5;
    #pragma unroll
    for (int i = 0; i < NV; i++) {
        float x = v[i];
        #pragma unroll
        for (int o = 16; o; o >>= 1) x += __shfl_xor_sync(0xffffffffu, x, o);
        if (lane == 0) sbuf[i*8 + wid] = x;
    }
    __syncthreads();
    #pragma unroll
    for (int i = 0; i < NV; i++) {
        float s = 0.f;
        #pragma unroll
        for (int j = 0; j < 8; j++) s += sbuf[i*8 + j];
        v[i] = s;
    }
    __syncthreads();
}

// ===================== K1: per-batch prep (grid 4 x BS) =====================
__global__ void k1_prep(const float* __restrict__ k_r, const float* __restrict__ m_t,
                        const float* __restrict__ e_t, const float* __restrict__ m_er,
                        const float* __restrict__ gW,  const float* __restrict__ gb,
                        const float* __restrict__ oW,  const float* __restrict__ ob) {
    __shared__ float sbuf[48];
    __shared__ __align__(16) float s_cat[2*W];
    const int b = blockIdx.y, t = threadIdx.x;

    const float wm = tanhf(m_t[b*W + t]);
    const float me = m_er[b*W + t];
    const float ex = expf(e_t[b*W + t]);            // erase softmax, no max pass

    float kv[R];
    #pragma unroll
    for (int r = 0; r < R; r++) kv[r] = tanhf(k_r[(b*R + r)*W + t]);

    float v[6];
    v[0] = ex;
    v[1] = wm * gW[t] + me * gW[W + t];
    #pragma unroll
    for (int r = 0; r < R; r++) v[2+r] = kv[r] * kv[r];
    blk_reduce_sum<6>(v, sbuf);

    const float g = 1.f / (1.f + expf(-(v[1] + gb[0])));
    s_cat[t]     = g * wm;
    s_cat[W + t] = (1.f - g) * me;

    if (blockIdx.x == 0) {
        g_wmer[b*W + t] = make_float2(wm, ex / v[0]);
        #pragma unroll
        for (int r = 0; r < R; r++) kv[r] /= (sqrtf(v[2+r]) + EPSF);
        g_kn4[b*W + t] = make_float4(kv[0], kv[1], kv[2], kv[3]);
    }
    __syncthreads();

    // MLP: 64 rows per block, 4 threads per row
    const int o = blockIdx.x * 64 + (t >> 2);
    const int p = t & 3;
    const float4* orow4 = (const float4*)(oW + (size_t)o * 2 * W);
    const float4* sc4   = (const float4*)s_cat;
    float acc = 0.f;
    #pragma unroll 8
    for (int i = 0; i < 32; i++) {
        const int j = 4*i + p;
        float4 ow = orow4[j], sc = sc4[j];
        acc += ow.x*sc.x + ow.y*sc.y + ow.z*sc.z + ow.w*sc.w;
    }
    acc += __shfl_xor_sync(0xffffffffu, acc, 1);
    acc += __shfl_xor_sync(0xffffffffu, acc, 2);
    if (p == 0) g_wk[b*W + o] = fmaxf(acc + ob[o], 0.f);
}

// ===================== K2: unnormalized write weights =====================
__global__ void k2_wdist(const float* __restrict__ mem) {
    __shared__ float s_wkn[W];
    __shared__ float sbuf[8];
    const int b = blockIdx.y, t = threadIdx.x;
    const int n0 = blockIdx.x * 512 + 2 * t;

    const float wk = g_wk[b*W + t];
    float v1[1] = { wk * wk };
    blk_reduce_sum<1>(v1, sbuf);
    s_wkn[t] = wk / (sqrtf(v1[0]) + EPSF);
    __syncthreads();

    const float2* mp = (const float2*)(mem + (size_t)b * W * N + n0);
    float2 sq = make_float2(0.f, 0.f), dot = make_float2(0.f, 0.f);
    #pragma unroll 16
    for (int w = 0; w < W; w++) {
        float2 mv = mp[(size_t)w * (N/2)];
        float  kn = s_wkn[w];
        sq.x  += mv.x * mv.x;  sq.y  += mv.y * mv.y;
        dot.x += mv.x * kn;    dot.y += mv.y * kn;
    }
    float2 e;
    e.x = expf(-dot.x / (sqrtf(sq.x) + EPSF));
    e.y = expf(-dot.y / (sqrtf(sq.y) + EPSF));
    *(float2*)&g_we[b*N + n0] = e;

    float z[1] = { e.x + e.y };
    blk_reduce_sum<1>(z, sbuf);
    if (t == 0) g_Zw_part[b*CH + blockIdx.x] = z[0];
}

// ===================== K4 fused: M_new + read weights + partial m_read ====
// Block owns a 64-column chunk. Pass 1 streams mem, writes M_new to global
// AND keeps the chunk in smem. After per-column norms/dots, pass 2 computes
// this chunk's contribution to m_read entirely from smem (no M_new re-read).
__global__ void __launch_bounds__(256)
k4_fused(const float* __restrict__ mem, float* __restrict__ Mnew,
         float* __restrict__ rwt) {
    extern __shared__ __align__(16) float smem[];
    float4* s_kn   = (float4*)smem;                   // [256]
    float*  s_mn   = smem + 1024;                     // [256][68]
    float*  s_e    = smem + 1024 + 256*SMN_STRIDE;    // [4][64]
    float2* s_wmer = (float2*)(s_e + 256);            // [256]
    float*  s_part = (float*)(s_wmer + 256);          // [256*5]
    float*  s_red  = s_part + 256*5;                  // [8]

    const int b = blockIdx.y, c = blockIdx.x, t = threadIdx.x;
    const int n0  = c * CCOL;
    const int col = t & 63;        // column within chunk
    const int seg = t >> 6;        // w-segment 0..3 (64 w each)

    s_kn[t]   = g_kn4[b*W + t];
    s_wmer[t] = g_wmer[b*W + t];

    float zw = 0.f;
    #pragma unroll
    for (int k = 0; k < CH; k++) zw += g_Zw_part[b*CH + k];
    const float wwt = g_we[b*N + n0 + col] / zw;
    __syncthreads();

    // ---- pass 1: this thread handles (col, w in [seg*64, seg*64+64)) ----
    const float* mp = mem  + (size_t)b * W * N + n0 + col + (size_t)(seg*64) * N;
    float*       op = Mnew + (size_t)b * W * N + n0 + col + (size_t)(seg*64) * N;
    float sq = 0.f, d0 = 0.f, d1 = 0.f, d2 = 0.f, d3 = 0.f;
    #pragma unroll 16
    for (int wi = 0; wi < 64; wi++) {
        const int w = seg*64 + wi;
        float  v  = mp[(size_t)wi * N];
        float2 we = s_wmer[w];
        float4 k  = s_kn[w];
        float  mn = v * (1.f - we.y * wwt) + we.x * wwt;
        op[(size_t)wi * N] = mn;
        s_mn[w * SMN_STRIDE + col] = mn;
        sq += mn * mn;
        d0 += mn * k.x; d1 += mn * k.y; d2 += mn * k.z; d3 += mn * k.w;
    }
    float* pp = s_part + t * 5;
    pp[0] = sq; pp[1] = d0; pp[2] = d1; pp[3] = d2; pp[4] = d3;
    __syncthreads();

    // ---- per-column finalize: combine 4 segments, exp, stash e ----
    if (t < 64) {
        float acc[5] = {0.f, 0.f, 0.f, 0.f, 0.f};
        #pragma unroll
        for (int s = 0; s < 4; s++) {
            const float* q = s_part + (s*64 + t) * 5;
            #pragma unroll
            for (int k = 0; k < 5; k++) acc[k] += q[k];
        }
        const float inv = 1.f / (sqrtf(acc[0]) + EPSF);
        float e[R];
        #pragma unroll
        for (int r = 0; r < R; r++) {
            e[r] = expf(acc[1+r] * inv);
            s_e[r*64 + t] = e[r];
            rwt[((size_t)b*R + r)*N + n0 + t] = e[r];   // unnormalized; k5 fixes
        }
        // partial Zr over this chunk's 64 columns (2 warps)
        #pragma unroll
        for (int r = 0; r < R; r++) {
            float z = e[r];
            #pragma unroll
            for (int o = 16; o; o >>= 1) z += __shfl_xor_sync(0xffffffffu, z, o);
            if ((t & 31) == 0) s_red[(t >> 5)*4 + r] = z;
        }
    }
    __syncthreads();
    if (t == 0) {
        float4 z = make_float4(s_red[0]+s_red[4], s_red[1]+s_red[5],
                               s_red[2]+s_red[6], s_red[3]+s_red[7]);
        *(float4*)&g_Zr_part[((size_t)b*NC + c)*R] = z;
    }

    // ---- pass 2: thread t == w; dot chunk row with 4 e-rows (all smem) ----
    const float4* mnrow = (const float4*)(s_mn + t * SMN_STRIDE);
    const float4* e0 = (const float4*)(s_e);
    const float4* e1 = (const float4*)(s_e + 64);
    const float4* e2 = (const float4*)(s_e + 128);
    const float4* e3 = (const float4*)(s_e + 192);
    float a0 = 0.f, a1 = 0.f, a2 = 0.f, a3 = 0.f;
    #pragma unroll
    for (int j = 0; j < 16; j++) {
        float4 v  = mnrow[j];
        float4 q0 = e0[j], q1 = e1[j], q2 = e2[j], q3 = e3[j];
        a0 += v.x*q0.x + v.y*q0.y + v.z*q0.z + v.w*q0.w;
        a1 += v.x*q1.x + v.y*q1.y + v.z*q1.z + v.w*q1.w;
        a2 += v.x*q2.x + v.y*q2.y + v.z*q2.z + v.w*q2.w;
        a3 += v.x*q3.x + v.y*q3.y + v.z*q3.z + v.w*q3.w;
    }
    *(float4*)&g_mr_part[(((size_t)b*NC + c)*W + t)*R] =
        make_float4(a0, a1, a2, a3);
}

// ===================== K5: finalize m_read + normalize rwt ================
__global__ void k5_final(float* __restrict__ rwt, float* __restrict__ mread) {
    const int b = blockIdx.x, t = threadIdx.x;

    // Zr (redundant per thread; 128 broadcast loads from L1)
    float4 Z = make_float4(0.f, 0.f, 0.f, 0.f);
    #pragma unroll
    for (int c = 0; c < NC; c++) {
        float4 z = *(const float4*)&g_Zr_part[((size_t)b*NC + c)*R];
        Z.x += z.x; Z.y += z.y; Z.z += z.z; Z.w += z.w;
    }
    const float i0 = 1.f/Z.x, i1 = 1.f/Z.y, i2 = 1.f/Z.z, i3 = 1.f/Z.w;

    // m_read: t == w, sum NC partials
    float4 a = make_float4(0.f, 0.f, 0.f, 0.f);
    #pragma unroll
    for (int c = 0; c < NC; c++) {
        float4 p = *(const float4*)&g_mr_part[(((size_t)b*NC + c)*W + t)*R];
        a.x += p.x; a.y += p.y; a.z += p.z; a.w += p.w;
    }
    float* mo = mread + (size_t)b * R * W + t;
    mo[0]   = a.x * i0;
    mo[W]   = a.y * i1;
    mo[2*W] = a.z * i2;
    mo[3*W] = a.w * i3;

    // rwt in-place normalize: 2048 float4 per batch
    const float invZ[R] = { i0, i1, i2, i3 };
    float4* rp = (float4*)(rwt + (size_t)b * R * N);
    #pragma unroll
    for (int k = 0; k < 8; k++) {
        const int i = t + k * 256;
        const float s = invZ[i >> 9];          // i / (N/4)
        float4 v = rp[i];
        v.x *= s; v.y *= s; v.z *= s; v.w *= s;
        rp[i] = v;
    }
}

// ===================== launch =====================
extern "C" void kernel_launch(void* const* d_in, const int* in_sizes, int n_in,
                              void* d_out, int out_size) {
    const float* k_r   = (const float*)d_in[0];
    const float* m_t   = (const float*)d_in[1];
    const float* e_t   = (const float*)d_in[2];
    const float* m_er  = (const float*)d_in[3];
    const float* mem   = (const float*)d_in[4];
    const float* gW    = (const float*)d_in[5];
    const float* gb    = (const float*)d_in[6];
    const float* oW    = (const float*)d_in[7];
    const float* ob    = (const float*)d_in[8];

    float* out   = (float*)d_out;
    float* mread = out;               // (BS,R,W)
    float* Mnew  = out + OFF_MNEW;    // (BS,W,N)
    float* rwt   = out + OFF_RWT;     // (BS,R,N)

    static bool attr_set = false;
    if (!attr_set) {
        cudaFuncSetAttribute(k4_fused, cudaFuncAttributeMaxDynamicSharedMemorySize,
                             K4_SMEM);
        attr_set = true;
    }

    k1_prep <<<dim3(4,  BS), 256>>>(k_r, m_t, e_t, m_er, gW, gb, oW, ob);
    k2_wdist<<<dim3(CH, BS), 256>>>(mem);
    k4_fused<<<dim3(NC, BS), 256, K4_SMEM>>>(mem, Mnew, rwt);
    k5_final<<<BS, 256>>>(rwt, mread);
}

// round 6
// speedup vs baseline: 1.5483x; 1.5483x over previous
#include <cuda_runtime.h>
#include <math.h>

// Fixed shapes for BlurredMem_61950608278069
#define BS 128
#define W  256
#define N  2048
#define R  4
#define EPSF 1e-8f
#define CH 4                  // k2 n-chunks (512 n per block)
#define CCOL 32               // k4 chunk columns
#define NC (N/CCOL)           // 64 chunks
#define SMS 33                // s_mn row stride (odd -> low bank conflicts)

// Output layout: m_read (BS,R,W) | M_new (BS,W,N) | read_wt (BS,R,N)
#define OFF_MNEW (BS*R*W)
#define OFF_RWT  (BS*R*W + BS*W*N)

// -------- scratch (device globals) --------
__device__ float  g_wk[BS*W];          // UNNORMALIZED write key (relu'd)
__device__ float2 g_wmer[BS*W];        // (write_m, erase_vec)
__device__ float4 g_kn4[BS*W];         // normalized read keys (r packed)
__device__ float  g_we[BS*N];          // exp(-cos) unnormalized write weights
__device__ float  g_Zw_part[BS*CH];    // per-block partial sums of g_we
__device__ float  g_Zr_part[BS*NC*R];  // per-chunk partial Zr
__device__ float  g_mr_part[BS*NC*W*R];// per-chunk partial m_read (32MB)

// -------- block reduction: warp shuffles + one smem pass (256 threads) ----
template<int NV>
__device__ __forceinline__ void blk_reduce_sum(float (&v)[NV], float* sbuf) {
    const int lane = threadIdx.x & 31, wid = threadIdx.x >> 5;
    #pragma unroll
    for (int i = 0; i < NV; i++) {
        float x = v[i];
        #pragma unroll
        for (int o = 16; o; o >>= 1) x += __shfl_xor_sync(0xffffffffu, x, o);
        if (lane == 0) sbuf[i*8 + wid] = x;
    }
    __syncthreads();
    #pragma unroll
    for (int i = 0; i < NV; i++) {
        float s = 0.f;
        #pragma unroll
        for (int j = 0; j < 8; j++) s += sbuf[i*8 + j];
        v[i] = s;
    }
    __syncthreads();
}

// ===================== K1: per-batch prep (grid 4 x BS) =====================
__global__ void k1_prep(const float* __restrict__ k_r, const float* __restrict__ m_t,
                        const float* __restrict__ e_t, const float* __restrict__ m_er,
                        const float* __restrict__ gW,  const float* __restrict__ gb,
                        const float* __restrict__ oW,  const float* __restrict__ ob) {
    __shared__ float sbuf[48];
    __shared__ __align__(16) float s_cat[2*W];
    const int b = blockIdx.y, t = threadIdx.x;

    const float wm = tanhf(m_t[b*W + t]);
    const float me = m_er[b*W + t];
    const float ex = expf(e_t[b*W + t]);            // erase softmax, no max pass

    float kv[R];
    #pragma unroll
    for (int r = 0; r < R; r++) kv[r] = tanhf(k_r[(b*R + r)*W + t]);

    float v[6];
    v[0] = ex;
    v[1] = wm * gW[t] + me * gW[W + t];
    #pragma unroll
    for (int r = 0; r < R; r++) v[2+r] = kv[r] * kv[r];
    blk_reduce_sum<6>(v, sbuf);

    const float g = 1.f / (1.f + expf(-(v[1] + gb[0])));
    s_cat[t]     = g * wm;
    s_cat[W + t] = (1.f - g) * me;

    if (blockIdx.x == 0) {
        g_wmer[b*W + t] = make_float2(wm, ex / v[0]);
        #pragma unroll
        for (int r = 0; r < R; r++) kv[r] /= (sqrtf(v[2+r]) + EPSF);
        g_kn4[b*W + t] = make_float4(kv[0], kv[1], kv[2], kv[3]);
    }
    __syncthreads();

    // MLP: 64 rows per block, 4 threads per row
    const int o = blockIdx.x * 64 + (t >> 2);
    const int p = t & 3;
    const float4* orow4 = (const float4*)(oW + (size_t)o * 2 * W);
    const float4* sc4   = (const float4*)s_cat;
    float acc = 0.f;
    #pragma unroll 8
    for (int i = 0; i < 32; i++) {
        const int j = 4*i + p;
        float4 ow = orow4[j], sc = sc4[j];
        acc += ow.x*sc.x + ow.y*sc.y + ow.z*sc.z + ow.w*sc.w;
    }
    acc += __shfl_xor_sync(0xffffffffu, acc, 1);
    acc += __shfl_xor_sync(0xffffffffu, acc, 2);
    if (p == 0) g_wk[b*W + o] = fmaxf(acc + ob[o], 0.f);
}

// ===================== K2: unnormalized write weights =====================
__global__ void k2_wdist(const float* __restrict__ mem) {
    __shared__ float s_wkn[W];
    __shared__ float sbuf[8];
    const int b = blockIdx.y, t = threadIdx.x;
    const int n0 = blockIdx.x * 512 + 2 * t;

    const float wk = g_wk[b*W + t];
    float v1[1] = { wk * wk };
    blk_reduce_sum<1>(v1, sbuf);
    s_wkn[t] = wk / (sqrtf(v1[0]) + EPSF);
    __syncthreads();

    const float2* mp = (const float2*)(mem + (size_t)b * W * N + n0);
    float2 sq = make_float2(0.f, 0.f), dot = make_float2(0.f, 0.f);
    #pragma unroll 16
    for (int w = 0; w < W; w++) {
        float2 mv = mp[(size_t)w * (N/2)];
        float  kn = s_wkn[w];
        sq.x  += mv.x * mv.x;  sq.y  += mv.y * mv.y;
        dot.x += mv.x * kn;    dot.y += mv.y * kn;
    }
    float2 e;
    e.x = expf(-dot.x / (sqrtf(sq.x) + EPSF));
    e.y = expf(-dot.y / (sqrtf(sq.y) + EPSF));
    *(float2*)&g_we[b*N + n0] = e;

    float z[1] = { e.x + e.y };
    blk_reduce_sum<1>(z, sbuf);
    if (t == 0) g_Zw_part[b*CH + blockIdx.x] = z[0];
}

// ===================== K4 fused v2: M_new + read wts + partial m_read =====
// Block owns a 32-column chunk. Pass 1 == proven k4 float2 loop (16 colpairs
// x 16 w-groups) + smem stash. Pass 2 dots the stashed chunk with the 4
// e-rows entirely in smem -> per-chunk partial m_read. No M_new re-read.
__global__ void __launch_bounds__(256)
k4_fused(const float* __restrict__ mem, float* __restrict__ Mnew,
         float* __restrict__ rwt) {
    __shared__ float4 s_kn[W];                 // 4 KB
    __shared__ float2 s_wmer[W];               // 2 KB
    __shared__ float  s_mn[W*SMS];             // 33.8 KB (row-major, stride 33)
    __shared__ float  s_e[R][CCOL];            // 512 B
    __shared__ float  s_part[128*10];          // 5 KB

    const int b = blockIdx.y, c = blockIdx.x, t = threadIdx.x;
    const int n0  = c * CCOL;
    const int c2  = t & 15;          // colpair 0..15
    const int grp = t >> 4;          // w-group 0..15 (16 rows each)
    const int lane = t & 31, q = t >> 5;

    s_kn[t]   = g_kn4[b*W + t];
    s_wmer[t] = g_wmer[b*W + t];

    float zw = 0.f;
    #pragma unroll
    for (int k = 0; k < CH; k++) zw += g_Zw_part[b*CH + k];

    const int col0 = 2 * c2;
    float2 wev = *(const float2*)&g_we[b*N + n0 + col0];
    const float2 wwt = make_float2(wev.x / zw, wev.y / zw);
    __syncthreads();

    // ---- pass 1 ----
    const size_t base = (size_t)b * W * N + n0 + col0;
    float2 sq = make_float2(0.f, 0.f);
    float2 d0 = sq, d1 = sq, d2 = sq, d3 = sq;
    #pragma unroll
    for (int wi = 0; wi < 16; wi++) {
        const int w = grp * 16 + wi;
        float2 mv = *(const float2*)(mem + base + (size_t)w * N);
        float2 we = s_wmer[w];
        float4 k  = s_kn[w];
        float2 mn;
        mn.x = mv.x * (1.f - we.y * wwt.x) + we.x * wwt.x;
        mn.y = mv.y * (1.f - we.y * wwt.y) + we.x * wwt.y;
        *(float2*)(Mnew + base + (size_t)w * N) = mn;
        s_mn[w * SMS + col0]     = mn.x;
        s_mn[w * SMS + col0 + 1] = mn.y;
        sq.x += mn.x * mn.x;  sq.y += mn.y * mn.y;
        d0.x += mn.x * k.x;   d0.y += mn.y * k.x;
        d1.x += mn.x * k.y;   d1.y += mn.y * k.y;
        d2.x += mn.x * k.z;   d2.y += mn.y * k.z;
        d3.x += mn.x * k.w;   d3.y += mn.y * k.w;
    }
    // combine grp pairs (lanes L, L+16 share colpair) via shuffle
    float pv[10] = { sq.x, sq.y, d0.x, d0.y, d1.x, d1.y,
                     d2.x, d2.y, d3.x, d3.y };
    #pragma unroll
    for (int j = 0; j < 10; j++)
        pv[j] += __shfl_down_sync(0xffffffffu, pv[j], 16);
    if (lane < 16) {
        float* pp = s_part + (q * 16 + lane) * 10;
        #pragma unroll
        for (int j = 0; j < 10; j++) pp[j] = pv[j];
    }
    __syncthreads();

    // ---- per-column finalize (warp 0; col = t) ----
    if (t < CCOL) {
        const int cp = t >> 1, comp = t & 1;
        float acc[5] = {0.f, 0.f, 0.f, 0.f, 0.f};
        #pragma unroll
        for (int qq = 0; qq < 8; qq++) {
            const float* pp = s_part + (qq * 16 + cp) * 10;
            #pragma unroll
            for (int j = 0; j < 5; j++) acc[j] += pp[comp + 2*j];
        }
        const float inv = 1.f / (sqrtf(acc[0]) + EPSF);
        float e[R];
        #pragma unroll
        for (int r = 0; r < R; r++) {
            e[r] = expf(acc[1+r] * inv);
            s_e[r][t] = e[r];
            rwt[((size_t)b*R + r)*N + n0 + t] = e[r];  // unnormalized; k5 fixes
        }
        #pragma unroll
        for (int r = 0; r < R; r++) {
            float z = e[r];
            #pragma unroll
            for (int o = 16; o; o >>= 1) z += __shfl_xor_sync(0xffffffffu, z, o);
            e[r] = z;
        }
        if (t == 0)
            *(float4*)&g_Zr_part[((size_t)b*NC + c)*R] =
                make_float4(e[0], e[1], e[2], e[3]);
    }
    __syncthreads();

    // ---- pass 2: thread t == w; 32 conflict-free scalar LDS + broadcasts ----
    float a0 = 0.f, a1 = 0.f, a2 = 0.f, a3 = 0.f;
    const float* mr = s_mn + t * SMS;
    #pragma unroll
    for (int col = 0; col < CCOL; col++) {
        float mn = mr[col];
        a0 += mn * s_e[0][col];
        a1 += mn * s_e[1][col];
        a2 += mn * s_e[2][col];
        a3 += mn * s_e[3][col];
    }
    *(float4*)&g_mr_part[(((size_t)b*NC + c)*W + t)*R] =
        make_float4(a0, a1, a2, a3);
}

// ===================== K5: finalize m_read + normalize rwt ================
__global__ void k5_final(float* __restrict__ rwt, float* __restrict__ mread) {
    const int b = blockIdx.y, part = blockIdx.x, t = threadIdx.x;

    float4 Z = make_float4(0.f, 0.f, 0.f, 0.f);
    #pragma unroll 8
    for (int c = 0; c < NC; c++) {
        float4 z = *(const float4*)&g_Zr_part[((size_t)b*NC + c)*R];
        Z.x += z.x; Z.y += z.y; Z.z += z.z; Z.w += z.w;
    }
    const float i0 = 1.f/Z.x, i1 = 1.f/Z.y, i2 = 1.f/Z.z, i3 = 1.f/Z.w;

    if (part == 0) {
        // m_read: t == w, sum NC partials
        float4 a = make_float4(0.f, 0.f, 0.f, 0.f);
        #pragma unroll 8
        for (int c = 0; c < NC; c++) {
            float4 p = *(const float4*)&g_mr_part[(((size_t)b*NC + c)*W + t)*R];
            a.x += p.x; a.y += p.y; a.z += p.z; a.w += p.w;
        }
        float* mo = mread + (size_t)b * R * W + t;
        mo[0]   = a.x * i0;
        mo[W]   = a.y * i1;
        mo[2*W] = a.z * i2;
        mo[3*W] = a.w * i3;
    } else {
        // rwt in-place normalize: 2048 float4 per batch
        const float invZ[R] = { i0, i1, i2, i3 };
        float4* rp = (float4*)(rwt + (size_t)b * R * N);
        #pragma unroll
        for (int k = 0; k < 8; k++) {
            const int i = t + k * 256;
            const float s = invZ[i >> 9];
            float4 v = rp[i];
            v.x *= s; v.y *= s; v.z *= s; v.w *= s;
            rp[i] = v;
        }
    }
}

// ===================== launch =====================
extern "C" void kernel_launch(void* const* d_in, const int* in_sizes, int n_in,
                              void* d_out, int out_size) {
    const float* k_r   = (const float*)d_in[0];
    const float* m_t   = (const float*)d_in[1];
    const float* e_t   = (const float*)d_in[2];
    const float* m_er  = (const float*)d_in[3];
    const float* mem   = (const float*)d_in[4];
    const float* gW    = (const float*)d_in[5];
    const float* gb    = (const float*)d_in[6];
    const float* oW    = (const float*)d_in[7];
    const float* ob    = (const float*)d_in[8];

    float* out   = (float*)d_out;
    float* mread = out;               // (BS,R,W)
    float* Mnew  = out + OFF_MNEW;    // (BS,W,N)
    float* rwt   = out + OFF_RWT;     // (BS,R,N)

    k1_prep <<<dim3(4,  BS), 256>>>(k_r, m_t, e_t, m_er, gW, gb, oW, ob);
    k2_wdist<<<dim3(CH, BS), 256>>>(mem);
    k4_fused<<<dim3(NC, BS), 256>>>(mem, Mnew, rwt);
    k5_final<<<dim3(2,  BS), 256>>>(rwt, mread);
}

// round 7
// speedup vs baseline: 1.6134x; 1.0421x over previous
#include <cuda_runtime.h>
#include <math.h>

// Fixed shapes for BlurredMem_61950608278069
#define BS 128
#define W  256
#define N  2048
#define R  4
#define EPSF 1e-8f
#define CH 4                  // k2 n-chunks (512 n per block)
#define CCOL 32               // k4 sub-chunk columns
#define NSUB 4                // sub-chunks per block
#define NC2 16                // k4 blocks per batch (N / (CCOL*NSUB))
#define SMS 33                // s_mn row stride (odd -> low bank conflicts)

// Output layout: m_read (BS,R,W) | M_new (BS,W,N) | read_wt (BS,R,N)
#define OFF_MNEW (BS*R*W)
#define OFF_RWT  (BS*R*W + BS*W*N)

// -------- scratch (device globals) --------
__device__ float  g_wk[BS*W];           // UNNORMALIZED write key (relu'd)
__device__ float2 g_wmer[BS*W];         // (write_m, erase_vec)
__device__ float4 g_kn4[BS*W];          // normalized read keys (r packed)
__device__ float  g_we[BS*N];           // exp(-cos) unnormalized write weights
__device__ float  g_Zw_part[BS*CH];     // per-block partial sums of g_we
__device__ float  g_Zr_part[BS*NC2*R];  // per-block partial Zr
__device__ float  g_mr_part[BS*NC2*W*R];// per-block partial m_read (8MB)

// -------- block reduction: warp shuffles + one smem pass (256 threads) ----
template<int NV>
__device__ __forceinline__ void blk_reduce_sum(float (&v)[NV], float* sbuf) {
    const int lane = threadIdx.x & 31, wid = threadIdx.x >> 5;
    #pragma unroll
    for (int i = 0; i < NV; i++) {
        float x = v[i];
        #pragma unroll
        for (int o = 16; o; o >>= 1) x += __shfl_xor_sync(0xffffffffu, x, o);
        if (lane == 0) sbuf[i*8 + wid] = x;
    }
    __syncthreads();
    #pragma unroll
    for (int i = 0; i < NV; i++) {
        float s = 0.f;
        #pragma unroll
        for (int j = 0; j < 8; j++) s += sbuf[i*8 + j];
        v[i] = s;
    }
    __syncthreads();
}

// ===================== K1: per-batch prep (grid 4 x BS) =====================
__global__ void k1_prep(const float* __restrict__ k_r, const float* __restrict__ m_t,
                        const float* __restrict__ e_t, const float* __restrict__ m_er,
                        const float* __restrict__ gW,  const float* __restrict__ gb,
                        const float* __restrict__ oW,  const float* __restrict__ ob) {
    __shared__ float sbuf[48];
    __shared__ __align__(16) float s_cat[2*W];
    const int b = blockIdx.y, t = threadIdx.x;

    const float wm = tanhf(m_t[b*W + t]);
    const float me = m_er[b*W + t];
    const float ex = expf(e_t[b*W + t]);            // erase softmax, no max pass

    float kv[R];
    #pragma unroll
    for (int r = 0; r < R; r++) kv[r] = tanhf(k_r[(b*R + r)*W + t]);

    float v[6];
    v[0] = ex;
    v[1] = wm * gW[t] + me * gW[W + t];
    #pragma unroll
    for (int r = 0; r < R; r++) v[2+r] = kv[r] * kv[r];
    blk_reduce_sum<6>(v, sbuf);

    const float g = 1.f / (1.f + expf(-(v[1] + gb[0])));
    s_cat[t]     = g * wm;
    s_cat[W + t] = (1.f - g) * me;

    if (blockIdx.x == 0) {
        g_wmer[b*W + t] = make_float2(wm, ex / v[0]);
        #pragma unroll
        for (int r = 0; r < R; r++) kv[r] /= (sqrtf(v[2+r]) + EPSF);
        g_kn4[b*W + t] = make_float4(kv[0], kv[1], kv[2], kv[3]);
    }
    __syncthreads();

    // MLP: 64 rows per block, 4 threads per row
    const int o = blockIdx.x * 64 + (t >> 2);
    const int p = t & 3;
    const float4* orow4 = (const float4*)(oW + (size_t)o * 2 * W);
    const float4* sc4   = (const float4*)s_cat;
    float acc = 0.f;
    #pragma unroll 8
    for (int i = 0; i < 32; i++) {
        const int j = 4*i + p;
        float4 ow = orow4[j], sc = sc4[j];
        acc += ow.x*sc.x + ow.y*sc.y + ow.z*sc.z + ow.w*sc.w;
    }
    acc += __shfl_xor_sync(0xffffffffu, acc, 1);
    acc += __shfl_xor_sync(0xffffffffu, acc, 2);
    if (p == 0) g_wk[b*W + o] = fmaxf(acc + ob[o], 0.f);
}

// ===================== K2: unnormalized write weights =====================
__global__ void k2_wdist(const float* __restrict__ mem) {
    __shared__ float s_wkn[W];
    __shared__ float sbuf[8];
    const int b = blockIdx.y, t = threadIdx.x;
    const int n0 = blockIdx.x * 512 + 2 * t;

    const float wk = g_wk[b*W + t];
    float v1[1] = { wk * wk };
    blk_reduce_sum<1>(v1, sbuf);
    s_wkn[t] = wk / (sqrtf(v1[0]) + EPSF);
    __syncthreads();

    const float2* mp = (const float2*)(mem + (size_t)b * W * N + n0);
    float2 sq = make_float2(0.f, 0.f), dot = make_float2(0.f, 0.f);
    #pragma unroll 16
    for (int w = 0; w < W; w++) {
        float2 mv = mp[(size_t)w * (N/2)];
        float  kn = s_wkn[w];
        sq.x  += mv.x * mv.x;  sq.y  += mv.y * mv.y;
        dot.x += mv.x * kn;    dot.y += mv.y * kn;
    }
    float2 e;
    e.x = expf(-dot.x / (sqrtf(sq.x) + EPSF));
    e.y = expf(-dot.y / (sqrtf(sq.y) + EPSF));
    *(float2*)&g_we[b*N + n0] = e;

    float z[1] = { e.x + e.y };
    blk_reduce_sum<1>(z, sbuf);
    if (t == 0) g_Zw_part[b*CH + blockIdx.x] = z[0];
}

// ===================== K4 fused v3: 4 sub-chunks per block ================
// Block owns 128 columns, processed as 4 sub-chunks of 32. m_read partials
// accumulate in registers across sub-chunks -> one 8MB partial array.
__global__ void __launch_bounds__(256)
k4_fused(const float* __restrict__ mem, float* __restrict__ Mnew,
         float* __restrict__ rwt) {
    __shared__ float4 s_kn[W];                 // 4 KB
    __shared__ float2 s_wmer[W];               // 2 KB
    __shared__ float  s_mn[W*SMS];             // 33.8 KB
    __shared__ float  s_e[R][CCOL];            // 512 B
    __shared__ float  s_part[128*10];          // 5 KB

    const int b = blockIdx.y, c = blockIdx.x, t = threadIdx.x;
    const int c2  = t & 15;          // colpair 0..15
    const int grp = t >> 4;          // w-group 0..15 (16 rows each)
    const int lane = t & 31, q = t >> 5;

    s_kn[t]   = g_kn4[b*W + t];
    s_wmer[t] = g_wmer[b*W + t];

    float zw = 0.f;
    #pragma unroll
    for (int k = 0; k < CH; k++) zw += g_Zw_part[b*CH + k];
    __syncthreads();

    float a0 = 0.f, a1 = 0.f, a2 = 0.f, a3 = 0.f;   // m_read partials (t == w)
    float zacc[R] = {0.f, 0.f, 0.f, 0.f};           // Zr partials (warp0)

    #pragma unroll
    for (int sub = 0; sub < NSUB; sub++) {
        const int n0   = (c * NSUB + sub) * CCOL;
        const int col0 = 2 * c2;

        float2 wev = *(const float2*)&g_we[b*N + n0 + col0];
        const float2 wwt = make_float2(wev.x / zw, wev.y / zw);

        // ---- pass 1 ----
        const size_t base = (size_t)b * W * N + n0 + col0;
        float2 sq = make_float2(0.f, 0.f);
        float2 d0 = sq, d1 = sq, d2 = sq, d3 = sq;
        #pragma unroll
        for (int wi = 0; wi < 16; wi++) {
            const int w = grp * 16 + wi;
            float2 mv = *(const float2*)(mem + base + (size_t)w * N);
            float2 we = s_wmer[w];
            float4 k  = s_kn[w];
            float2 mn;
            mn.x = mv.x * (1.f - we.y * wwt.x) + we.x * wwt.x;
            mn.y = mv.y * (1.f - we.y * wwt.y) + we.x * wwt.y;
            *(float2*)(Mnew + base + (size_t)w * N) = mn;
            s_mn[w * SMS + col0]     = mn.x;
            s_mn[w * SMS + col0 + 1] = mn.y;
            sq.x += mn.x * mn.x;  sq.y += mn.y * mn.y;
            d0.x += mn.x * k.x;   d0.y += mn.y * k.x;
            d1.x += mn.x * k.y;   d1.y += mn.y * k.y;
            d2.x += mn.x * k.z;   d2.y += mn.y * k.z;
            d3.x += mn.x * k.w;   d3.y += mn.y * k.w;
        }
        float pv[10] = { sq.x, sq.y, d0.x, d0.y, d1.x, d1.y,
                         d2.x, d2.y, d3.x, d3.y };
        #pragma unroll
        for (int j = 0; j < 10; j++)
            pv[j] += __shfl_down_sync(0xffffffffu, pv[j], 16);
        if (lane < 16) {
            float* pp = s_part + (q * 16 + lane) * 10;
            #pragma unroll
            for (int j = 0; j < 10; j++) pp[j] = pv[j];
        }
        __syncthreads();

        // ---- per-column finalize (warp 0; col = t) ----
        if (t < CCOL) {
            const int cp = t >> 1, comp = t & 1;
            float acc[5] = {0.f, 0.f, 0.f, 0.f, 0.f};
            #pragma unroll
            for (int qq = 0; qq < 8; qq++) {
                const float* pp = s_part + (qq * 16 + cp) * 10;
                #pragma unroll
                for (int j = 0; j < 5; j++) acc[j] += pp[comp + 2*j];
            }
            const float inv = 1.f / (sqrtf(acc[0]) + EPSF);
            #pragma unroll
            for (int r = 0; r < R; r++) {
                float e = expf(acc[1+r] * inv);
                s_e[r][t] = e;
                rwt[((size_t)b*R + r)*N + n0 + t] = e;  // unnormalized
                float z = e;
                #pragma unroll
                for (int o = 16; o; o >>= 1)
                    z += __shfl_xor_sync(0xffffffffu, z, o);
                zacc[r] += z;
            }
        }
        __syncthreads();

        // ---- pass 2: thread t == w; accumulate across sub-chunks ----
        const float* mr = s_mn + t * SMS;
        #pragma unroll
        for (int col = 0; col < CCOL; col++) {
            float mn = mr[col];
            a0 += mn * s_e[0][col];
            a1 += mn * s_e[1][col];
            a2 += mn * s_e[2][col];
            a3 += mn * s_e[3][col];
        }
        if (sub < NSUB-1) __syncthreads();   // protect s_mn/s_e reuse
    }

    if (t == 0)
        *(float4*)&g_Zr_part[((size_t)b*NC2 + c)*R] =
            make_float4(zacc[0], zacc[1], zacc[2], zacc[3]);
    *(float4*)&g_mr_part[(((size_t)b*NC2 + c)*W + t)*R] =
        make_float4(a0, a1, a2, a3);
}

// ===================== K5: finalize m_read + normalize rwt ================
// grid (9, BS): part 0 sums m_read partials; parts 1..8 normalize rwt slices
__global__ void k5_final(float* __restrict__ rwt, float* __restrict__ mread) {
    const int b = blockIdx.y, part = blockIdx.x, t = threadIdx.x;

    float4 Z = make_float4(0.f, 0.f, 0.f, 0.f);
    #pragma unroll
    for (int c = 0; c < NC2; c++) {
        float4 z = *(const float4*)&g_Zr_part[((size_t)b*NC2 + c)*R];
        Z.x += z.x; Z.y += z.y; Z.z += z.z; Z.w += z.w;
    }
    const float i0 = 1.f/Z.x, i1 = 1.f/Z.y, i2 = 1.f/Z.z, i3 = 1.f/Z.w;

    if (part == 0) {
        float4 a = make_float4(0.f, 0.f, 0.f, 0.f);
        #pragma unroll
        for (int c = 0; c < NC2; c++) {
            float4 p = *(const float4*)&g_mr_part[(((size_t)b*NC2 + c)*W + t)*R];
            a.x += p.x; a.y += p.y; a.z += p.z; a.w += p.w;
        }
        float* mo = mread + (size_t)b * R * W + t;
        mo[0]   = a.x * i0;
        mo[W]   = a.y * i1;
        mo[2*W] = a.z * i2;
        mo[3*W] = a.w * i3;
    } else {
        // slice of 256 float4 out of 2048 per batch
        const float invZ[R] = { i0, i1, i2, i3 };
        float4* rp = (float4*)(rwt + (size_t)b * R * N);
        const int i = t + (part - 1) * 256;
        const float s = invZ[i >> 9];
        float4 v = rp[i];
        v.x *= s; v.y *= s; v.z *= s; v.w *= s;
        rp[i] = v;
    }
}

// ===================== launch =====================
extern "C" void kernel_launch(void* const* d_in, const int* in_sizes, int n_in,
                              void* d_out, int out_size) {
    const float* k_r   = (const float*)d_in[0];
    const float* m_t   = (const float*)d_in[1];
    const float* e_t   = (const float*)d_in[2];
    const float* m_er  = (const float*)d_in[3];
    const float* mem   = (const float*)d_in[4];
    const float* gW    = (const float*)d_in[5];
    const float* gb    = (const float*)d_in[6];
    const float* oW    = (const float*)d_in[7];
    const float* ob    = (const float*)d_in[8];

    float* out   = (float*)d_out;
    float* mread = out;               // (BS,R,W)
    float* Mnew  = out + OFF_MNEW;    // (BS,W,N)
    float* rwt   = out + OFF_RWT;     // (BS,R,N)

    k1_prep <<<dim3(4,   BS), 256>>>(k_r, m_t, e_t, m_er, gW, gb, oW, ob);
    k2_wdist<<<dim3(CH,  BS), 256>>>(mem);
    k4_fused<<<dim3(NC2, BS), 256>>>(mem, Mnew, rwt);
    k5_final<<<dim3(9,   BS), 256>>>(rwt, mread);
}